// round 16
// baseline (speedup 1.0000x reference)
#include <cuda_runtime.h>
#include <cuda_fp16.h>
#include <math.h>
#include <stdint.h>

// Problem constants
#define BB 64
#define NN 128
#define JJ 512
#define DD 1024
#define HH 4096
#define MM (BB * NN)          // 8192 rows
#define SCALE 0.03125f        // 1024^-0.5
#define EPS 1e-8f
#define LN_EPS 1e-5f

// ---------------------------------------------------------------------------
// Scratch (device globals; no allocations allowed)
// ---------------------------------------------------------------------------
__device__ float g_slots[MM * DD];
__device__ float g_attn [MM * JJ];
__device__ float g_dotsb[JJ];
__device__ float g_part [MM * 4];

__device__ __align__(16) __half g_gi16  [MM * 3 * DD];
__device__ __align__(16) __half g_gh16  [MM * 3 * DD];
__device__ __align__(16) __half g_txn16 [JJ * DD];
__device__ __align__(16) __half g_k16   [JJ * DD];
__device__ __align__(16) __half g_v16   [JJ * DD];
__device__ __align__(16) __half g_kq16  [JJ * DD];
__device__ __align__(16) __half g_vW16  [JJ * 3 * DD];
__device__ __align__(16) __half g_vWT16 [3 * DD * JJ];
__device__ __align__(16) __half g_attn16[MM * JJ];
__device__ __align__(16) __half g_hid16 [MM * HH];
__device__ __align__(16) __half g_lnb16 [MM * DD];
__device__ __align__(16) __half g_slots16[MM * DD];
__device__ __align__(16) __half g_Wq16  [DD * DD];
__device__ __align__(16) __half g_WqT16 [DD * DD];
__device__ __align__(16) __half g_Wk16  [DD * DD];
__device__ __align__(16) __half g_Wv16  [DD * DD];
__device__ __align__(16) __half g_Wih16 [3 * DD * DD];
__device__ __align__(16) __half g_Whh16 [3 * DD * DD];
__device__ __align__(16) __half g_W116  [HH * DD];
__device__ __align__(16) __half g_W216  [DD * HH];

// ---------------------------------------------------------------------------
// Helpers
// ---------------------------------------------------------------------------
__device__ __forceinline__ float warp_sum(float v) {
    #pragma unroll
    for (int o = 16; o; o >>= 1) v += __shfl_xor_sync(0xFFFFFFFFu, v, o);
    return v;
}

__device__ __forceinline__ uint32_t smem_u32(const void* p) {
    uint32_t a;
    asm("{ .reg .u64 t; cvta.to.shared.u64 t, %1; cvt.u32.u64 %0, t; }"
        : "=r"(a) : "l"(p));
    return a;
}

__device__ __forceinline__ float tanh_fast(float x) {
    float y;
    asm("tanh.approx.f32 %0, %1;" : "=f"(y) : "f"(x));
    return y;
}
__device__ __forceinline__ float sigm_fast(float x) {
    return 1.f / (1.f + __expf(-x));
}

// m16n8k16 fp16 MMA, fp32 accumulate (sm_80+ baseline)
__device__ __forceinline__ void mma_f16(float* c,
                                        uint32_t a0, uint32_t a1, uint32_t a2, uint32_t a3,
                                        uint32_t b0, uint32_t b1) {
    asm volatile(
        "mma.sync.aligned.m16n8k16.row.col.f32.f16.f16.f32 "
        "{%0,%1,%2,%3}, {%4,%5,%6,%7}, {%8,%9}, {%0,%1,%2,%3};"
        : "+f"(c[0]), "+f"(c[1]), "+f"(c[2]), "+f"(c[3])
        : "r"(a0), "r"(a1), "r"(a2), "r"(a3), "r"(b0), "r"(b1));
}

__device__ __forceinline__ void ldsm_x4(uint32_t& r0, uint32_t& r1,
                                        uint32_t& r2, uint32_t& r3, uint32_t addr) {
    asm volatile("ldmatrix.sync.aligned.m8n8.x4.shared.b16 {%0,%1,%2,%3}, [%4];"
                 : "=r"(r0), "=r"(r1), "=r"(r2), "=r"(r3) : "r"(addr));
}

#define CP16(smem, gptr) \
    asm volatile("cp.async.cg.shared.global [%0], [%1], 16;" \
                 :: "r"(smem), "l"(gptr))
#define CP_COMMIT() asm volatile("cp.async.commit_group;")
#define CP_WAIT2()  asm volatile("cp.async.wait_group 2;")
#define CP_WAIT1()  asm volatile("cp.async.wait_group 1;")
#define CP_WAIT0()  asm volatile("cp.async.wait_group 0;")

// ---------------------------------------------------------------------------
// Batched fp32 -> fp16 conversion of all weights + inputs (one launch).
// Segment boundaries in 16B (4-float) units; all compile-time.
// ---------------------------------------------------------------------------
#define S_WQ   262144                       // DD*DD/4
#define S_WK   (S_WQ + 262144)
#define S_WV   (S_WK + 262144)
#define S_WIH  (S_WV + 786432)              // 3*DD*DD/4
#define S_WHH  (S_WIH + 786432)
#define S_W1   (S_WHH + 1048576)            // HH*DD/4
#define S_W2   (S_W1 + 1048576)
#define S_IN   (S_W2 + 2097152)             // MM*DD/4
#define F2H_BLOCKS (S_IN / 256)             // 25600

__global__ void f2h_all_kernel(
    const float* __restrict__ wq, const float* __restrict__ wk,
    const float* __restrict__ wv, const float* __restrict__ wih,
    const float* __restrict__ whh, const float* __restrict__ w1,
    const float* __restrict__ w2, const float* __restrict__ inp,
    __half* dq, __half* dk, __half* dv, __half* dih,
    __half* dhh, __half* d1, __half* d2, __half* dslots) {
    const int i = blockIdx.x * 256 + threadIdx.x;
    const float* s; __half* d; int off;
    if (i < S_WV) {
        if (i < S_WQ)      { s = wq;  d = dq;  off = i; }
        else if (i < S_WK) { s = wk;  d = dk;  off = i - S_WQ; }
        else               { s = wv;  d = dv;  off = i - S_WK; }
    } else if (i < S_W1) {
        if (i < S_WIH)     { s = wih; d = dih; off = i - S_WV; }
        else if (i < S_WHH){ s = whh; d = dhh; off = i - S_WIH; }
        else               { s = w1;  d = d1;  off = i - S_WHH; }
    } else {
        if (i < S_W2)      { s = w2;  d = d2;  off = i - S_W1; }
        else               { s = inp; d = dslots; off = i - S_W2; }
    }
    float4 v = ((const float4*)s)[off];
    __half2 h01 = __floats2half2_rn(v.x, v.y);
    __half2 h23 = __floats2half2_rn(v.z, v.w);
    ((uint2*)d)[off] = make_uint2(*(uint32_t*)&h01, *(uint32_t*)&h23);
}

// ---------------------------------------------------------------------------
// dots bias: dotsb[j] = SCALE * sum_d k16[j,d] * bq[d]. Grid JJ x 256 thr.
// ---------------------------------------------------------------------------
__global__ void dotsb_kernel(const __half* __restrict__ k,
                             const float* __restrict__ bq,
                             float* __restrict__ out) {
    const int row = blockIdx.x;
    const int t = threadIdx.x;
    const __half* kr = k + (size_t)row * DD;
    float s = 0.f;
    #pragma unroll
    for (int u = 0; u < 4; u++) {
        const int d = t * 4 + u;
        s += __half2float(kr[d]) * bq[d];
    }
    s = warp_sum(s);
    __shared__ float ws[8];
    if ((t & 31) == 0) ws[t >> 5] = s;
    __syncthreads();
    if (t == 0) {
        float S = 0.f;
        #pragma unroll
        for (int w = 0; w < 8; w++) S += ws[w];
        out[row] = S * SCALE;
    }
}

// ---------------------------------------------------------------------------
// LayerNorm: fp32 in -> fp16 out. One block per row, D=1024, 256 threads.
// ---------------------------------------------------------------------------
__global__ void ln_kernel(const float* __restrict__ x, __half* __restrict__ y,
                          const float* __restrict__ g, const float* __restrict__ b) {
    const int row = blockIdx.x;
    const int t = threadIdx.x;
    const float4* xr = (const float4*)(x + (size_t)row * DD);
    float4 v = xr[t];
    float s = v.x + v.y + v.z + v.w;
    float q = v.x * v.x + v.y * v.y + v.z * v.z + v.w * v.w;
    s = warp_sum(s);
    q = warp_sum(q);
    __shared__ float s1[8], s2[8];
    if ((t & 31) == 0) { s1[t >> 5] = s; s2[t >> 5] = q; }
    __syncthreads();
    float S = 0.f, Q = 0.f;
    #pragma unroll
    for (int w = 0; w < 8; w++) { S += s1[w]; Q += s2[w]; }
    const float mean = S * (1.f / DD);
    const float var  = Q * (1.f / DD) - mean * mean;
    const float inv  = rsqrtf(var + LN_EPS);
    float4 gv = ((const float4*)g)[t];
    float4 bv = ((const float4*)b)[t];
    __half2 o01 = __floats2half2_rn((v.x - mean) * inv * gv.x + bv.x,
                                    (v.y - mean) * inv * gv.y + bv.y);
    __half2 o23 = __floats2half2_rn((v.z - mean) * inv * gv.z + bv.z,
                                    (v.w - mean) * inv * gv.w + bv.w);
    *(uint2*)(y + (size_t)row * DD + t * 4) =
        make_uint2(*(uint32_t*)&o01, *(uint32_t*)&o23);
}

// ---------------------------------------------------------------------------
// Tensor-core FP16 NT GEMM, 3-stage cp.async pipeline (dynamic SMEM).
// C[M,N] = alpha*A[M,K]@B[N,K]^T (+bias)(relu)(+resid); fp32 and/or fp16 out.
// CTA 128x128, BK=32, 256 threads (8 warps, warp tile 64x32).
// ---------------------------------------------------------------------------
#define LDPH 40                       // halves per SMEM row (32 + 8 pad)
#define ROWB (LDPH * 2)               // 80 bytes per row
#define HALFBUF (128 * ROWB)          // 10240 bytes (one operand tile)
#define SBUF (2 * HALFBUF)            // 20480 bytes per stage (A + B)
#define SMEM_DYN (3 * SBUF)           // 61440 bytes

__global__ __launch_bounds__(256, 2)
void gemm_h_kernel(const __half* __restrict__ A, const __half* __restrict__ Bw,
                   float* __restrict__ C, __half* __restrict__ C16,
                   int M, int N, int K,
                   const float* __restrict__ bias, const float* __restrict__ resid,
                   float alpha, int relu) {
    extern __shared__ __align__(16) char smem_raw[];
    const uint32_t sbase = smem_u32(smem_raw);

    const int tid  = threadIdx.x;
    const int warp = tid >> 5;
    const int lane = tid & 31;
    const int gid  = lane >> 2;
    const int tig  = lane & 3;
    const int wm = (warp >> 2) * 64;
    const int wn = (warp & 3) * 32;
    const int bm = blockIdx.y * 128;
    const int bn = blockIdx.x * 128;

    const int sr = tid >> 2;          // staging rows 0..63 (slot 0), +64
    const int sg = tid & 3;           // 16B group in row

    const uint32_t sa0 = sbase + (uint32_t)(sr * ROWB + sg * 16);
    const uint32_t sa1 = sa0 + 64 * ROWB;
    const uint32_t sb0 = sa0 + HALFBUF;
    const uint32_t sb1 = sa1 + HALFBUF;

    const uint32_t a_base0 = sbase +
        (uint32_t)((wm + (lane & 15)) * ROWB + (lane >> 4) * 16);
    const uint32_t b_base0 = sbase + HALFBUF +
        (uint32_t)((wn + ((lane >> 4) << 3) + (lane & 7)) * ROWB +
                   ((lane >> 3) & 1) * 16);

    float acc[4][4][4];
    #pragma unroll
    for (int mf = 0; mf < 4; mf++)
        #pragma unroll
        for (int nf = 0; nf < 4; nf++)
            #pragma unroll
            for (int u = 0; u < 4; u++) acc[mf][nf][u] = 0.f;

    const int nch = K >> 5;

    #define STAGE(c, buf) do {                                            \
        const int _k0 = (c) << 5;                                         \
        const uint32_t _off = (uint32_t)(buf) * SBUF;                     \
        CP16(sa0 + _off, A  + (size_t)(bm + sr) * K + _k0 + sg * 8);      \
        CP16(sa1 + _off, A  + (size_t)(bm + sr + 64) * K + _k0 + sg * 8); \
        CP16(sb0 + _off, Bw + (size_t)(bn + sr) * K + _k0 + sg * 8);      \
        CP16(sb1 + _off, Bw + (size_t)(bn + sr + 64) * K + _k0 + sg * 8); \
        CP_COMMIT();                                                      \
    } while (0)

    STAGE(0, 0);
    if (nch > 1) STAGE(1, 1);

    int buf = 0;
    for (int c = 0; c < nch; c++) {
        const int ahead = nch - 1 - c;
        if (ahead >= 2) STAGE(c + 2, (buf + 2 >= 3) ? buf - 1 : buf + 2);
        if (ahead >= 2)      { CP_WAIT2(); }
        else if (ahead == 1) { CP_WAIT1(); }
        else                 { CP_WAIT0(); }
        __syncthreads();

        const uint32_t aB = a_base0 + (uint32_t)buf * SBUF;
        const uint32_t bB = b_base0 + (uint32_t)buf * SBUF;
        #pragma unroll
        for (int ks = 0; ks < 2; ks++) {
            const uint32_t koff = (uint32_t)(ks * 16 * 2);
            uint32_t b[4][2];
            ldsm_x4(b[0][0], b[0][1], b[1][0], b[1][1], bB + koff);
            ldsm_x4(b[2][0], b[2][1], b[3][0], b[3][1],
                    bB + koff + 16 * ROWB);
            #pragma unroll
            for (int mf = 0; mf < 4; mf++) {
                uint32_t a0, a1, a2, a3;
                ldsm_x4(a0, a1, a2, a3,
                        aB + koff + (uint32_t)(mf * 16 * ROWB));
                #pragma unroll
                for (int nf = 0; nf < 4; nf++)
                    mma_f16(acc[mf][nf], a0, a1, a2, a3, b[nf][0], b[nf][1]);
            }
        }
        __syncthreads();
        buf = (buf + 1 >= 3) ? 0 : buf + 1;
    }
    #undef STAGE

    // Epilogue
    #pragma unroll
    for (int mf = 0; mf < 4; mf++) {
        #pragma unroll
        for (int nf = 0; nf < 4; nf++) {
            const int cc = bn + wn + nf * 8 + 2 * tig;
            float bx = 0.f, by = 0.f;
            if (bias) { bx = bias[cc]; by = bias[cc + 1]; }
            #pragma unroll
            for (int h = 0; h < 2; h++) {
                const int row = bm + wm + mf * 16 + gid + h * 8;
                float v0 = acc[mf][nf][2 * h + 0] * alpha + bx;
                float v1 = acc[mf][nf][2 * h + 1] * alpha + by;
                if (relu) { v0 = fmaxf(v0, 0.f); v1 = fmaxf(v1, 0.f); }
                if (resid) {
                    float2 rr = *(const float2*)(resid + (size_t)row * N + cc);
                    v0 += rr.x; v1 += rr.y;
                }
                if (C) {
                    float2 ov = { v0, v1 };
                    *(float2*)(C + (size_t)row * N + cc) = ov;
                }
                if (C16) {
                    __half2 hv = __floats2half2_rn(v0, v1);
                    *(uint32_t*)(C16 + (size_t)row * N + cc) = *(uint32_t*)&hv;
                }
            }
        }
    }
}

// ---------------------------------------------------------------------------
// fp16 transpose (rows x cols) -> (cols x rows), 32x32 tiles
// ---------------------------------------------------------------------------
__global__ void transpose_h_kernel(const __half* __restrict__ in,
                                   __half* __restrict__ out, int R, int C) {
    __shared__ __half tile[32][34];
    const int c0 = blockIdx.x * 32;
    const int r0 = blockIdx.y * 32;
    for (int dy = threadIdx.y; dy < 32; dy += 8)
        tile[dy][threadIdx.x] = in[(size_t)(r0 + dy) * C + c0 + threadIdx.x];
    __syncthreads();
    for (int dy = threadIdx.y; dy < 32; dy += 8)
        out[(size_t)(c0 + dy) * R + r0 + threadIdx.x] = tile[threadIdx.x][dy];
}

// ---------------------------------------------------------------------------
// Two-phase softmax over the slots axis (i), then row renorm over j.
// Phase 1: grid (4, BB), 512 threads. CTA = (j-quarter q, batch b).
// Column softmax over i for 128 j's; write e*cinv fp16; per-quarter row
// partial sums (fixed-order, deterministic) -> g_part[row][q].
// ---------------------------------------------------------------------------
__global__ void softmax_phase1(const float* __restrict__ attn,
                               __half* __restrict__ out,
                               float* __restrict__ partials) {
    __shared__ __half sh_e[NN][128];
    __shared__ float sm[4][128], ssum[4][128], gM[128], gSinv[128];
    const int q = blockIdx.x, b = blockIdx.y;
    const int t = threadIdx.x;
    const int jl = t & 127, ig = t >> 7;           // j-local, i-group
    const int j = q * 128 + jl;
    const float* base = attn + (size_t)b * NN * JJ + j;

    float m = -3.0e38f, s = 0.f;
    for (int i = ig; i < NN; i += 4) {
        float x = base[(size_t)i * JJ];
        float nm = fmaxf(m, x);
        s = s * __expf(m - nm) + __expf(x - nm);
        m = nm;
    }
    sm[ig][jl] = m;
    ssum[ig][jl] = s;
    __syncthreads();
    if (ig == 0) {
        float M = sm[0][jl];
        #pragma unroll
        for (int p = 1; p < 4; p++) M = fmaxf(M, sm[p][jl]);
        float S = 0.f;
        #pragma unroll
        for (int p = 0; p < 4; p++) S += ssum[p][jl] * __expf(sm[p][jl] - M);
        gM[jl] = M;
        gSinv[jl] = 1.f / S;
    }
    __syncthreads();
    const float M = gM[jl], Sinv = gSinv[jl];
    __half* o = out + (size_t)b * NN * JJ + j;
    for (int i = ig; i < NN; i += 4) {
        float e = __expf(base[(size_t)i * JJ] - M) * Sinv;
        __half h = __float2half_rn(e);
        o[(size_t)i * JJ] = h;
        sh_e[i][jl] = h;
    }
    __syncthreads();
    // per-row partial sums over this quarter's 128 j's (fixed order)
    const int w = t >> 5, lane = t & 31;
    for (int i = w; i < NN; i += 16) {
        float s2 = 0.f;
        #pragma unroll
        for (int c = lane; c < 128; c += 32)
            s2 += __half2float(sh_e[i][c]);
        s2 = warp_sum(s2);
        if (lane == 0)
            partials[(size_t)(b * NN + i) * 4 + q] = s2;
    }
}

// ---------------------------------------------------------------------------
// Phase 2: grid MM/4, 256 threads. 4 rows per CTA, 64 threads per row.
// attn16[row][j] = (v + EPS) / (sum4(partials) + J*EPS)
// ---------------------------------------------------------------------------
__global__ void softmax_phase2(__half* __restrict__ attn16,
                               const float* __restrict__ partials) {
    const int row = blockIdx.x * 4 + (threadIdx.x >> 6);
    const int c = threadIdx.x & 63;
    const float* p = partials + (size_t)row * 4;
    const float rinv = 1.f / (p[0] + p[1] + p[2] + p[3] + (float)JJ * EPS);
    __half2* a = (__half2*)(attn16 + (size_t)row * JJ) + c;
    #pragma unroll
    for (int u = 0; u < 4; u++) {
        float2 f = __half22float2(a[u * 64]);
        a[u * 64] = __floats2half2_rn((f.x + EPS) * rinv, (f.y + EPS) * rinv);
    }
}

// ---------------------------------------------------------------------------
// Fused GRU + LayerNorm(ff): one block per row. 256 threads x 4 elements.
// ---------------------------------------------------------------------------
__global__ void gru_ln_kernel(const __half* __restrict__ gi,
                              const __half* __restrict__ gh,
                              float* __restrict__ slots,
                              __half* __restrict__ lnb,
                              const float* __restrict__ g,
                              const float* __restrict__ b) {
    const int row = blockIdx.x;
    const int t = threadIdx.x;
    const size_t o3 = (size_t)row * (3 * DD) + t * 4;
    const size_t o1 = (size_t)row * DD + t * 4;

    uint2 uir = *(const uint2*)(gi + o3);
    uint2 uhr = *(const uint2*)(gh + o3);
    uint2 uiz = *(const uint2*)(gi + o3 + DD);
    uint2 uhz = *(const uint2*)(gh + o3 + DD);
    uint2 uin = *(const uint2*)(gi + o3 + 2 * DD);
    uint2 uhn = *(const uint2*)(gh + o3 + 2 * DD);
    float4 hv = *(const float4*)(slots + o1);
    float h[4] = { hv.x, hv.y, hv.z, hv.w };

    float nv[4];
    #pragma unroll
    for (int u = 0; u < 2; u++) {
        float2 ir = __half22float2(((const __half2*)&uir)[u]);
        float2 hr = __half22float2(((const __half2*)&uhr)[u]);
        float2 iz = __half22float2(((const __half2*)&uiz)[u]);
        float2 hz = __half22float2(((const __half2*)&uhz)[u]);
        float2 in_ = __half22float2(((const __half2*)&uin)[u]);
        float2 hn = __half22float2(((const __half2*)&uhn)[u]);
        float r0 = sigm_fast(ir.x + hr.x), r1 = sigm_fast(ir.y + hr.y);
        float z0 = sigm_fast(iz.x + hz.x), z1 = sigm_fast(iz.y + hz.y);
        float n0 = tanh_fast(in_.x + r0 * hn.x);
        float n1 = tanh_fast(in_.y + r1 * hn.y);
        nv[2 * u + 0] = (1.f - z0) * n0 + z0 * h[2 * u + 0];
        nv[2 * u + 1] = (1.f - z1) * n1 + z1 * h[2 * u + 1];
    }

    float4 ov = { nv[0], nv[1], nv[2], nv[3] };
    *(float4*)(slots + o1) = ov;

    float s = nv[0] + nv[1] + nv[2] + nv[3];
    float q = nv[0] * nv[0] + nv[1] * nv[1] + nv[2] * nv[2] + nv[3] * nv[3];
    s = warp_sum(s);
    q = warp_sum(q);
    __shared__ float s1[8], s2[8];
    if ((t & 31) == 0) { s1[t >> 5] = s; s2[t >> 5] = q; }
    __syncthreads();
    float S = 0.f, Q = 0.f;
    #pragma unroll
    for (int w = 0; w < 8; w++) { S += s1[w]; Q += s2[w]; }
    const float mean = S * (1.f / DD);
    const float var  = Q * (1.f / DD) - mean * mean;
    const float inv  = rsqrtf(var + LN_EPS);
    float4 gv = ((const float4*)g)[t];
    float4 bv = ((const float4*)b)[t];
    __half2 l01 = __floats2half2_rn((nv[0] - mean) * inv * gv.x + bv.x,
                                    (nv[1] - mean) * inv * gv.y + bv.y);
    __half2 l23 = __floats2half2_rn((nv[2] - mean) * inv * gv.z + bv.z,
                                    (nv[3] - mean) * inv * gv.w + bv.w);
    *(uint2*)(lnb + o1) = make_uint2(*(uint32_t*)&l01, *(uint32_t*)&l23);
}

// ---------------------------------------------------------------------------
// Launch
// ---------------------------------------------------------------------------
static inline void gemm(const __half* A, const __half* B, float* C, __half* C16,
                        int M, int N, int K,
                        const float* bias, const float* resid, float alpha, int relu) {
    dim3 grid(N / 128, M / 128);
    gemm_h_kernel<<<grid, 256, SMEM_DYN>>>(A, B, C, C16, M, N, K, bias, resid,
                                           alpha, relu);
}

extern "C" void kernel_launch(void* const* d_in, const int* in_sizes, int n_in,
                              void* d_out, int out_size) {
    const float* inputs = (const float*)d_in[0];
    const float* texts  = (const float*)d_in[1];
    const float* Wq   = (const float*)d_in[2];  const float* bq   = (const float*)d_in[3];
    const float* Wk   = (const float*)d_in[4];  const float* bk   = (const float*)d_in[5];
    const float* Wv   = (const float*)d_in[6];  const float* bv   = (const float*)d_in[7];
    const float* W_ih = (const float*)d_in[8];  const float* b_ih = (const float*)d_in[9];
    const float* W_hh = (const float*)d_in[10]; const float* b_hh = (const float*)d_in[11];
    const float* W1   = (const float*)d_in[12]; const float* b1   = (const float*)d_in[13];
    const float* W2   = (const float*)d_in[14]; const float* b2   = (const float*)d_in[15];
    const float* gin  = (const float*)d_in[16]; const float* bein = (const float*)d_in[17];
    const float* gsl  = (const float*)d_in[18]; const float* besl = (const float*)d_in[19];
    const float* gff  = (const float*)d_in[20]; const float* beff = (const float*)d_in[21];

    cudaFuncSetAttribute(gemm_h_kernel, cudaFuncAttributeMaxDynamicSharedMemorySize,
                         SMEM_DYN);

    float *slots, *attn, *dotsb, *part;
    __half *gi16, *gh16;
    __half *txn16, *k16, *v16, *kq16, *vW16, *vWT16, *attn16, *hid16, *lnb16, *slots16;
    __half *Wq16, *WqT16, *Wk16, *Wv16, *Wih16, *Whh16, *W116, *W216;
    cudaGetSymbolAddress((void**)&slots,  g_slots);
    cudaGetSymbolAddress((void**)&attn,   g_attn);
    cudaGetSymbolAddress((void**)&dotsb,  g_dotsb);
    cudaGetSymbolAddress((void**)&part,   g_part);
    cudaGetSymbolAddress((void**)&gi16,   g_gi16);
    cudaGetSymbolAddress((void**)&gh16,   g_gh16);
    cudaGetSymbolAddress((void**)&txn16,  g_txn16);
    cudaGetSymbolAddress((void**)&k16,    g_k16);
    cudaGetSymbolAddress((void**)&v16,    g_v16);
    cudaGetSymbolAddress((void**)&kq16,   g_kq16);
    cudaGetSymbolAddress((void**)&vW16,   g_vW16);
    cudaGetSymbolAddress((void**)&vWT16,  g_vWT16);
    cudaGetSymbolAddress((void**)&attn16, g_attn16);
    cudaGetSymbolAddress((void**)&hid16,  g_hid16);
    cudaGetSymbolAddress((void**)&lnb16,  g_lnb16);
    cudaGetSymbolAddress((void**)&slots16,g_slots16);
    cudaGetSymbolAddress((void**)&Wq16,   g_Wq16);
    cudaGetSymbolAddress((void**)&WqT16,  g_WqT16);
    cudaGetSymbolAddress((void**)&Wk16,   g_Wk16);
    cudaGetSymbolAddress((void**)&Wv16,   g_Wv16);
    cudaGetSymbolAddress((void**)&Wih16,  g_Wih16);
    cudaGetSymbolAddress((void**)&Whh16,  g_Whh16);
    cudaGetSymbolAddress((void**)&W116,   g_W116);
    cudaGetSymbolAddress((void**)&W216,   g_W216);

    // Batched weight + input conversion (one launch)
    f2h_all_kernel<<<F2H_BLOCKS, 256>>>(Wq, Wk, Wv, W_ih, W_hh, W1, W2, inputs,
                                        Wq16, Wk16, Wv16, Wih16, Whh16,
                                        W116, W216, slots16);

    // slots = inputs (fp32 master copy)
    cudaMemcpyAsync(slots, inputs, (size_t)MM * DD * sizeof(float),
                    cudaMemcpyDeviceToDevice);

    // Prologue: texts_n = LN(texts); k/v; folded operands.
    ln_kernel<<<JJ, 256>>>(texts, txn16, gin, bein);
    gemm(txn16, Wk16, 0, k16, JJ, DD, DD, bk, 0, 1.f, 0);
    gemm(txn16, Wv16, 0, v16, JJ, DD, DD, bv, 0, 1.f, 0);
    // kq = k @ Wq  (via WqT as NT B operand)
    transpose_h_kernel<<<dim3(DD / 32, DD / 32), dim3(32, 8)>>>(Wq16, WqT16, DD, DD);
    gemm(k16, WqT16, 0, kq16, JJ, DD, DD, 0, 0, 1.f, 0);
    // dotsb[j] = SCALE * <k[j,:], bq>
    dotsb_kernel<<<JJ, 256>>>(k16, bq, dotsb);
    // vW = v @ W_ih^T  [J, 3D], then vWT [3D, J]
    gemm(v16, Wih16, 0, vW16, JJ, 3 * DD, DD, 0, 0, 1.f, 0);
    transpose_h_kernel<<<dim3(3 * DD / 32, JJ / 32), dim3(32, 8)>>>(vW16, vWT16,
                                                                    JJ, 3 * DD);

    for (int it = 0; it < 3; it++) {
        // lnb = LN(slots)
        ln_kernel<<<MM, 256>>>(slots, lnb16, gsl, besl);

        // dots = SCALE*(lnb @ kq^T) + dotsb  -> fp32  (q GEMM folded away)
        gemm(lnb16, kq16, attn, 0, MM, JJ, DD, dotsb, 0, SCALE, 0);

        // two-phase softmax over slots axis (+EPS) + renorm over j -> fp16
        softmax_phase1<<<dim3(4, BB), 512>>>(attn, attn16, part);
        softmax_phase2<<<MM / 4, 256>>>(attn16, part);

        // gi = attn @ vW + b_ih  (updates GEMM folded away; K=J=512)
        gemm(attn16, vWT16, 0, gi16, MM, 3 * DD, JJ, b_ih, 0, 1.f, 0);
        // gh = slots @ W_hh^T + b_hh
        gemm(slots16, Whh16, 0, gh16, MM, 3 * DD, DD, b_hh, 0, 1.f, 0);

        // fused GRU update + LayerNorm(ff) -> slots, lnb16
        gru_ln_kernel<<<MM, 256>>>(gi16, gh16, slots, lnb16, gff, beff);

        // FF: slots += relu(LN(slots) @ W1^T + b1) @ W2^T + b2
        gemm(lnb16, W116, 0, hid16, MM, HH, DD, b1, 0, 1.f, 1);
        float* outp = (it == 2) ? (float*)d_out : slots;
        gemm(hid16, W216, outp, slots16, MM, DD, HH, b2, slots, 1.f, 0);
    }
}

// round 17
// speedup vs baseline: 1.5339x; 1.5339x over previous
#include <cuda_runtime.h>
#include <cuda_fp16.h>
#include <math.h>
#include <stdint.h>

// Problem constants
#define BB 64
#define NN 128
#define JJ 512
#define DD 1024
#define HH 4096
#define MM (BB * NN)          // 8192 rows
#define SCALE 0.03125f        // 1024^-0.5
#define EPS 1e-8f
#define LN_EPS 1e-5f

// ---------------------------------------------------------------------------
// Scratch (device globals; no allocations allowed)
// ---------------------------------------------------------------------------
__device__ float g_slots[MM * DD];
__device__ float g_attn [MM * JJ];
__device__ float g_dotsb[JJ];

__device__ __align__(16) __half g_gi16  [MM * 3 * DD];
__device__ __align__(16) __half g_gh16  [MM * 3 * DD];
__device__ __align__(16) __half g_txn16 [JJ * DD];
__device__ __align__(16) __half g_k16   [JJ * DD];
__device__ __align__(16) __half g_v16   [JJ * DD];
__device__ __align__(16) __half g_kq16  [JJ * DD];
__device__ __align__(16) __half g_vW16  [JJ * 3 * DD];
__device__ __align__(16) __half g_vWT16 [3 * DD * JJ];
__device__ __align__(16) __half g_attn16[MM * JJ];
__device__ __align__(16) __half g_hid16 [MM * HH];
__device__ __align__(16) __half g_lnb16 [MM * DD];
__device__ __align__(16) __half g_slots16[MM * DD];
__device__ __align__(16) __half g_Wq16  [DD * DD];
__device__ __align__(16) __half g_WqT16 [DD * DD];
__device__ __align__(16) __half g_Wk16  [DD * DD];
__device__ __align__(16) __half g_Wv16  [DD * DD];
__device__ __align__(16) __half g_Wih16 [3 * DD * DD];
__device__ __align__(16) __half g_Whh16 [3 * DD * DD];
__device__ __align__(16) __half g_W116  [HH * DD];
__device__ __align__(16) __half g_W216  [DD * HH];

// ---------------------------------------------------------------------------
// Helpers
// ---------------------------------------------------------------------------
__device__ __forceinline__ float warp_sum(float v) {
    #pragma unroll
    for (int o = 16; o; o >>= 1) v += __shfl_xor_sync(0xFFFFFFFFu, v, o);
    return v;
}

__device__ __forceinline__ uint32_t smem_u32(const void* p) {
    uint32_t a;
    asm("{ .reg .u64 t; cvta.to.shared.u64 t, %1; cvt.u32.u64 %0, t; }"
        : "=r"(a) : "l"(p));
    return a;
}

__device__ __forceinline__ float tanh_fast(float x) {
    float y;
    asm("tanh.approx.f32 %0, %1;" : "=f"(y) : "f"(x));
    return y;
}
__device__ __forceinline__ float sigm_fast(float x) {
    return 1.f / (1.f + __expf(-x));
}

// m16n8k16 fp16 MMA, fp32 accumulate (sm_80+ baseline)
__device__ __forceinline__ void mma_f16(float* c,
                                        uint32_t a0, uint32_t a1, uint32_t a2, uint32_t a3,
                                        uint32_t b0, uint32_t b1) {
    asm volatile(
        "mma.sync.aligned.m16n8k16.row.col.f32.f16.f16.f32 "
        "{%0,%1,%2,%3}, {%4,%5,%6,%7}, {%8,%9}, {%0,%1,%2,%3};"
        : "+f"(c[0]), "+f"(c[1]), "+f"(c[2]), "+f"(c[3])
        : "r"(a0), "r"(a1), "r"(a2), "r"(a3), "r"(b0), "r"(b1));
}

__device__ __forceinline__ void ldsm_x4(uint32_t& r0, uint32_t& r1,
                                        uint32_t& r2, uint32_t& r3, uint32_t addr) {
    asm volatile("ldmatrix.sync.aligned.m8n8.x4.shared.b16 {%0,%1,%2,%3}, [%4];"
                 : "=r"(r0), "=r"(r1), "=r"(r2), "=r"(r3) : "r"(addr));
}

#define CP16(smem, gptr) \
    asm volatile("cp.async.cg.shared.global [%0], [%1], 16;" \
                 :: "r"(smem), "l"(gptr))
#define CP_COMMIT() asm volatile("cp.async.commit_group;")
#define CP_WAIT2()  asm volatile("cp.async.wait_group 2;")
#define CP_WAIT1()  asm volatile("cp.async.wait_group 1;")
#define CP_WAIT0()  asm volatile("cp.async.wait_group 0;")

// ---------------------------------------------------------------------------
// Batched fp32 -> fp16 conversion of all weights + inputs (one launch).
// Segment boundaries in 16B (4-float) units; all compile-time.
// ---------------------------------------------------------------------------
#define S_WQ   262144                       // DD*DD/4
#define S_WK   (S_WQ + 262144)
#define S_WV   (S_WK + 262144)
#define S_WIH  (S_WV + 786432)              // 3*DD*DD/4
#define S_WHH  (S_WIH + 786432)
#define S_W1   (S_WHH + 1048576)            // HH*DD/4
#define S_W2   (S_W1 + 1048576)
#define S_IN   (S_W2 + 2097152)             // MM*DD/4
#define F2H_BLOCKS (S_IN / 256)             // 25600

__global__ void f2h_all_kernel(
    const float* __restrict__ wq, const float* __restrict__ wk,
    const float* __restrict__ wv, const float* __restrict__ wih,
    const float* __restrict__ whh, const float* __restrict__ w1,
    const float* __restrict__ w2, const float* __restrict__ inp,
    __half* dq, __half* dk, __half* dv, __half* dih,
    __half* dhh, __half* d1, __half* d2, __half* dslots) {
    const int i = blockIdx.x * 256 + threadIdx.x;
    const float* s; __half* d; int off;
    if (i < S_WV) {
        if (i < S_WQ)      { s = wq;  d = dq;  off = i; }
        else if (i < S_WK) { s = wk;  d = dk;  off = i - S_WQ; }
        else               { s = wv;  d = dv;  off = i - S_WK; }
    } else if (i < S_W1) {
        if (i < S_WIH)     { s = wih; d = dih; off = i - S_WV; }
        else if (i < S_WHH){ s = whh; d = dhh; off = i - S_WIH; }
        else               { s = w1;  d = d1;  off = i - S_WHH; }
    } else {
        if (i < S_W2)      { s = w2;  d = d2;  off = i - S_W1; }
        else               { s = inp; d = dslots; off = i - S_W2; }
    }
    float4 v = ((const float4*)s)[off];
    __half2 h01 = __floats2half2_rn(v.x, v.y);
    __half2 h23 = __floats2half2_rn(v.z, v.w);
    ((uint2*)d)[off] = make_uint2(*(uint32_t*)&h01, *(uint32_t*)&h23);
}

// ---------------------------------------------------------------------------
// dots bias: dotsb[j] = SCALE * sum_d k16[j,d] * bq[d]. Grid JJ x 256 thr.
// ---------------------------------------------------------------------------
__global__ void dotsb_kernel(const __half* __restrict__ k,
                             const float* __restrict__ bq,
                             float* __restrict__ out) {
    const int row = blockIdx.x;
    const int t = threadIdx.x;
    const __half* kr = k + (size_t)row * DD;
    float s = 0.f;
    #pragma unroll
    for (int u = 0; u < 4; u++) {
        const int d = t * 4 + u;
        s += __half2float(kr[d]) * bq[d];
    }
    s = warp_sum(s);
    __shared__ float ws[8];
    if ((t & 31) == 0) ws[t >> 5] = s;
    __syncthreads();
    if (t == 0) {
        float S = 0.f;
        #pragma unroll
        for (int w = 0; w < 8; w++) S += ws[w];
        out[row] = S * SCALE;
    }
}

// ---------------------------------------------------------------------------
// LayerNorm: fp32 in -> fp16 out. One block per row, D=1024, 256 threads.
// ---------------------------------------------------------------------------
__global__ void ln_kernel(const float* __restrict__ x, __half* __restrict__ y,
                          const float* __restrict__ g, const float* __restrict__ b) {
    const int row = blockIdx.x;
    const int t = threadIdx.x;
    const float4* xr = (const float4*)(x + (size_t)row * DD);
    float4 v = xr[t];
    float s = v.x + v.y + v.z + v.w;
    float q = v.x * v.x + v.y * v.y + v.z * v.z + v.w * v.w;
    s = warp_sum(s);
    q = warp_sum(q);
    __shared__ float s1[8], s2[8];
    if ((t & 31) == 0) { s1[t >> 5] = s; s2[t >> 5] = q; }
    __syncthreads();
    float S = 0.f, Q = 0.f;
    #pragma unroll
    for (int w = 0; w < 8; w++) { S += s1[w]; Q += s2[w]; }
    const float mean = S * (1.f / DD);
    const float var  = Q * (1.f / DD) - mean * mean;
    const float inv  = rsqrtf(var + LN_EPS);
    float4 gv = ((const float4*)g)[t];
    float4 bv = ((const float4*)b)[t];
    __half2 o01 = __floats2half2_rn((v.x - mean) * inv * gv.x + bv.x,
                                    (v.y - mean) * inv * gv.y + bv.y);
    __half2 o23 = __floats2half2_rn((v.z - mean) * inv * gv.z + bv.z,
                                    (v.w - mean) * inv * gv.w + bv.w);
    *(uint2*)(y + (size_t)row * DD + t * 4) =
        make_uint2(*(uint32_t*)&o01, *(uint32_t*)&o23);
}

// ---------------------------------------------------------------------------
// Tensor-core FP16 NT GEMM, 3-stage cp.async pipeline (dynamic SMEM).
// C[M,N] = alpha*A[M,K]@B[N,K]^T (+bias)(relu)(+resid); fp32 and/or fp16 out.
// CTA 128x128, BK=32, 256 threads (8 warps, warp tile 64x32).
// ---------------------------------------------------------------------------
#define LDPH 40                       // halves per SMEM row (32 + 8 pad)
#define ROWB (LDPH * 2)               // 80 bytes per row
#define HALFBUF (128 * ROWB)          // 10240 bytes (one operand tile)
#define SBUF (2 * HALFBUF)            // 20480 bytes per stage (A + B)
#define SMEM_DYN (3 * SBUF)           // 61440 bytes

__global__ __launch_bounds__(256, 2)
void gemm_h_kernel(const __half* __restrict__ A, const __half* __restrict__ Bw,
                   float* __restrict__ C, __half* __restrict__ C16,
                   int M, int N, int K,
                   const float* __restrict__ bias, const float* __restrict__ resid,
                   float alpha, int relu) {
    extern __shared__ __align__(16) char smem_raw[];
    const uint32_t sbase = smem_u32(smem_raw);

    const int tid  = threadIdx.x;
    const int warp = tid >> 5;
    const int lane = tid & 31;
    const int gid  = lane >> 2;
    const int tig  = lane & 3;
    const int wm = (warp >> 2) * 64;
    const int wn = (warp & 3) * 32;
    const int bm = blockIdx.y * 128;
    const int bn = blockIdx.x * 128;

    const int sr = tid >> 2;          // staging rows 0..63 (slot 0), +64
    const int sg = tid & 3;           // 16B group in row

    const uint32_t sa0 = sbase + (uint32_t)(sr * ROWB + sg * 16);
    const uint32_t sa1 = sa0 + 64 * ROWB;
    const uint32_t sb0 = sa0 + HALFBUF;
    const uint32_t sb1 = sa1 + HALFBUF;

    const uint32_t a_base0 = sbase +
        (uint32_t)((wm + (lane & 15)) * ROWB + (lane >> 4) * 16);
    const uint32_t b_base0 = sbase + HALFBUF +
        (uint32_t)((wn + ((lane >> 4) << 3) + (lane & 7)) * ROWB +
                   ((lane >> 3) & 1) * 16);

    float acc[4][4][4];
    #pragma unroll
    for (int mf = 0; mf < 4; mf++)
        #pragma unroll
        for (int nf = 0; nf < 4; nf++)
            #pragma unroll
            for (int u = 0; u < 4; u++) acc[mf][nf][u] = 0.f;

    const int nch = K >> 5;

    #define STAGE(c, buf) do {                                            \
        const int _k0 = (c) << 5;                                         \
        const uint32_t _off = (uint32_t)(buf) * SBUF;                     \
        CP16(sa0 + _off, A  + (size_t)(bm + sr) * K + _k0 + sg * 8);      \
        CP16(sa1 + _off, A  + (size_t)(bm + sr + 64) * K + _k0 + sg * 8); \
        CP16(sb0 + _off, Bw + (size_t)(bn + sr) * K + _k0 + sg * 8);      \
        CP16(sb1 + _off, Bw + (size_t)(bn + sr + 64) * K + _k0 + sg * 8); \
        CP_COMMIT();                                                      \
    } while (0)

    STAGE(0, 0);
    if (nch > 1) STAGE(1, 1);

    int buf = 0;
    for (int c = 0; c < nch; c++) {
        const int ahead = nch - 1 - c;
        if (ahead >= 2) STAGE(c + 2, (buf + 2 >= 3) ? buf - 1 : buf + 2);
        if (ahead >= 2)      { CP_WAIT2(); }
        else if (ahead == 1) { CP_WAIT1(); }
        else                 { CP_WAIT0(); }
        __syncthreads();

        const uint32_t aB = a_base0 + (uint32_t)buf * SBUF;
        const uint32_t bB = b_base0 + (uint32_t)buf * SBUF;
        #pragma unroll
        for (int ks = 0; ks < 2; ks++) {
            const uint32_t koff = (uint32_t)(ks * 16 * 2);
            uint32_t b[4][2];
            ldsm_x4(b[0][0], b[0][1], b[1][0], b[1][1], bB + koff);
            ldsm_x4(b[2][0], b[2][1], b[3][0], b[3][1],
                    bB + koff + 16 * ROWB);
            #pragma unroll
            for (int mf = 0; mf < 4; mf++) {
                uint32_t a0, a1, a2, a3;
                ldsm_x4(a0, a1, a2, a3,
                        aB + koff + (uint32_t)(mf * 16 * ROWB));
                #pragma unroll
                for (int nf = 0; nf < 4; nf++)
                    mma_f16(acc[mf][nf], a0, a1, a2, a3, b[nf][0], b[nf][1]);
            }
        }
        __syncthreads();
        buf = (buf + 1 >= 3) ? 0 : buf + 1;
    }
    #undef STAGE

    // Epilogue
    #pragma unroll
    for (int mf = 0; mf < 4; mf++) {
        #pragma unroll
        for (int nf = 0; nf < 4; nf++) {
            const int cc = bn + wn + nf * 8 + 2 * tig;
            float bx = 0.f, by = 0.f;
            if (bias) { bx = bias[cc]; by = bias[cc + 1]; }
            #pragma unroll
            for (int h = 0; h < 2; h++) {
                const int row = bm + wm + mf * 16 + gid + h * 8;
                float v0 = acc[mf][nf][2 * h + 0] * alpha + bx;
                float v1 = acc[mf][nf][2 * h + 1] * alpha + by;
                if (relu) { v0 = fmaxf(v0, 0.f); v1 = fmaxf(v1, 0.f); }
                if (resid) {
                    float2 rr = *(const float2*)(resid + (size_t)row * N + cc);
                    v0 += rr.x; v1 += rr.y;
                }
                if (C) {
                    float2 ov = { v0, v1 };
                    *(float2*)(C + (size_t)row * N + cc) = ov;
                }
                if (C16) {
                    __half2 hv = __floats2half2_rn(v0, v1);
                    *(uint32_t*)(C16 + (size_t)row * N + cc) = *(uint32_t*)&hv;
                }
            }
        }
    }
}

// ---------------------------------------------------------------------------
// fp16 transpose (rows x cols) -> (cols x rows), 32x32 tiles
// ---------------------------------------------------------------------------
__global__ void transpose_h_kernel(const __half* __restrict__ in,
                                   __half* __restrict__ out, int R, int C) {
    __shared__ __half tile[32][34];
    const int c0 = blockIdx.x * 32;
    const int r0 = blockIdx.y * 32;
    for (int dy = threadIdx.y; dy < 32; dy += 8)
        tile[dy][threadIdx.x] = in[(size_t)(r0 + dy) * C + c0 + threadIdx.x];
    __syncthreads();
    for (int dy = threadIdx.y; dy < 32; dy += 8)
        out[(size_t)(c0 + dy) * R + r0 + threadIdx.x] = tile[threadIdx.x][dy];
}

// ---------------------------------------------------------------------------
// Fused softmax: per batch b, softmax over slots axis (i) per column j,
// +EPS, then renormalize over j, write fp16. One CTA per b, 512 threads.
// ---------------------------------------------------------------------------
#define SMEM_SOFTMAX (NN * JJ * 2)

__global__ void softmax_fused_kernel(const float* __restrict__ attn,
                                     __half* __restrict__ out) {
    extern __shared__ __half sh[];            // [NN][JJ] unnormalized exp
    __shared__ float cinv[JJ];
    __shared__ float rinv[NN];
    const int b = blockIdx.x;
    const int j = threadIdx.x;                // 0..511
    const float* base = attn + (size_t)b * NN * JJ;

    float m = -3.0e38f;
    for (int i = 0; i < NN; i++)
        m = fmaxf(m, base[(size_t)i * JJ + j]);

    float s = 0.f;
    for (int i = 0; i < NN; i++) {
        float e = __expf(base[(size_t)i * JJ + j] - m);
        s += e;
        sh[i * JJ + j] = __float2half_rn(e);
    }
    cinv[j] = 1.f / s;
    __syncthreads();

    const int warp = j >> 5, lane = j & 31;
    for (int r = warp * 8; r < warp * 8 + 8; r++) {
        float s2 = 0.f;
        for (int c = lane; c < JJ; c += 32)
            s2 += __half2float(sh[r * JJ + c]) * cinv[c];
        s2 = warp_sum(s2);
        if (lane == 0) rinv[r] = 1.f / (s2 + (float)JJ * EPS);
    }
    __syncthreads();

    __half* o = out + (size_t)b * NN * JJ;
    const float ci = cinv[j];
    for (int i = 0; i < NN; i++) {
        float v = (__half2float(sh[i * JJ + j]) * ci + EPS) * rinv[i];
        o[(size_t)i * JJ + j] = __float2half_rn(v);
    }
}

// ---------------------------------------------------------------------------
// Fused GRU + LayerNorm(ff): one block per row. 256 threads x 4 elements.
// ---------------------------------------------------------------------------
__global__ void gru_ln_kernel(const __half* __restrict__ gi,
                              const __half* __restrict__ gh,
                              float* __restrict__ slots,
                              __half* __restrict__ lnb,
                              const float* __restrict__ g,
                              const float* __restrict__ b) {
    const int row = blockIdx.x;
    const int t = threadIdx.x;
    const size_t o3 = (size_t)row * (3 * DD) + t * 4;
    const size_t o1 = (size_t)row * DD + t * 4;

    uint2 uir = *(const uint2*)(gi + o3);
    uint2 uhr = *(const uint2*)(gh + o3);
    uint2 uiz = *(const uint2*)(gi + o3 + DD);
    uint2 uhz = *(const uint2*)(gh + o3 + DD);
    uint2 uin = *(const uint2*)(gi + o3 + 2 * DD);
    uint2 uhn = *(const uint2*)(gh + o3 + 2 * DD);
    float4 hv = *(const float4*)(slots + o1);
    float h[4] = { hv.x, hv.y, hv.z, hv.w };

    float nv[4];
    #pragma unroll
    for (int u = 0; u < 2; u++) {
        float2 ir = __half22float2(((const __half2*)&uir)[u]);
        float2 hr = __half22float2(((const __half2*)&uhr)[u]);
        float2 iz = __half22float2(((const __half2*)&uiz)[u]);
        float2 hz = __half22float2(((const __half2*)&uhz)[u]);
        float2 in_ = __half22float2(((const __half2*)&uin)[u]);
        float2 hn = __half22float2(((const __half2*)&uhn)[u]);
        float r0 = sigm_fast(ir.x + hr.x), r1 = sigm_fast(ir.y + hr.y);
        float z0 = sigm_fast(iz.x + hz.x), z1 = sigm_fast(iz.y + hz.y);
        float n0 = tanh_fast(in_.x + r0 * hn.x);
        float n1 = tanh_fast(in_.y + r1 * hn.y);
        nv[2 * u + 0] = (1.f - z0) * n0 + z0 * h[2 * u + 0];
        nv[2 * u + 1] = (1.f - z1) * n1 + z1 * h[2 * u + 1];
    }

    float4 ov = { nv[0], nv[1], nv[2], nv[3] };
    *(float4*)(slots + o1) = ov;

    float s = nv[0] + nv[1] + nv[2] + nv[3];
    float q = nv[0] * nv[0] + nv[1] * nv[1] + nv[2] * nv[2] + nv[3] * nv[3];
    s = warp_sum(s);
    q = warp_sum(q);
    __shared__ float s1[8], s2[8];
    if ((t & 31) == 0) { s1[t >> 5] = s; s2[t >> 5] = q; }
    __syncthreads();
    float S = 0.f, Q = 0.f;
    #pragma unroll
    for (int w = 0; w < 8; w++) { S += s1[w]; Q += s2[w]; }
    const float mean = S * (1.f / DD);
    const float var  = Q * (1.f / DD) - mean * mean;
    const float inv  = rsqrtf(var + LN_EPS);
    float4 gv = ((const float4*)g)[t];
    float4 bv = ((const float4*)b)[t];
    __half2 l01 = __floats2half2_rn((nv[0] - mean) * inv * gv.x + bv.x,
                                    (nv[1] - mean) * inv * gv.y + bv.y);
    __half2 l23 = __floats2half2_rn((nv[2] - mean) * inv * gv.z + bv.z,
                                    (nv[3] - mean) * inv * gv.w + bv.w);
    *(uint2*)(lnb + o1) = make_uint2(*(uint32_t*)&l01, *(uint32_t*)&l23);
}

// ---------------------------------------------------------------------------
// Launch
// ---------------------------------------------------------------------------
static inline void gemm(const __half* A, const __half* B, float* C, __half* C16,
                        int M, int N, int K,
                        const float* bias, const float* resid, float alpha, int relu) {
    dim3 grid(N / 128, M / 128);
    gemm_h_kernel<<<grid, 256, SMEM_DYN>>>(A, B, C, C16, M, N, K, bias, resid,
                                           alpha, relu);
}

extern "C" void kernel_launch(void* const* d_in, const int* in_sizes, int n_in,
                              void* d_out, int out_size) {
    const float* inputs = (const float*)d_in[0];
    const float* texts  = (const float*)d_in[1];
    const float* Wq   = (const float*)d_in[2];  const float* bq   = (const float*)d_in[3];
    const float* Wk   = (const float*)d_in[4];  const float* bk   = (const float*)d_in[5];
    const float* Wv   = (const float*)d_in[6];  const float* bv   = (const float*)d_in[7];
    const float* W_ih = (const float*)d_in[8];  const float* b_ih = (const float*)d_in[9];
    const float* W_hh = (const float*)d_in[10]; const float* b_hh = (const float*)d_in[11];
    const float* W1   = (const float*)d_in[12]; const float* b1   = (const float*)d_in[13];
    const float* W2   = (const float*)d_in[14]; const float* b2   = (const float*)d_in[15];
    const float* gin  = (const float*)d_in[16]; const float* bein = (const float*)d_in[17];
    const float* gsl  = (const float*)d_in[18]; const float* besl = (const float*)d_in[19];
    const float* gff  = (const float*)d_in[20]; const float* beff = (const float*)d_in[21];

    cudaFuncSetAttribute(gemm_h_kernel, cudaFuncAttributeMaxDynamicSharedMemorySize,
                         SMEM_DYN);
    cudaFuncSetAttribute(softmax_fused_kernel,
                         cudaFuncAttributeMaxDynamicSharedMemorySize, SMEM_SOFTMAX);

    float *slots, *attn, *dotsb;
    __half *gi16, *gh16;
    __half *txn16, *k16, *v16, *kq16, *vW16, *vWT16, *attn16, *hid16, *lnb16, *slots16;
    __half *Wq16, *WqT16, *Wk16, *Wv16, *Wih16, *Whh16, *W116, *W216;
    cudaGetSymbolAddress((void**)&slots,  g_slots);
    cudaGetSymbolAddress((void**)&attn,   g_attn);
    cudaGetSymbolAddress((void**)&dotsb,  g_dotsb);
    cudaGetSymbolAddress((void**)&gi16,   g_gi16);
    cudaGetSymbolAddress((void**)&gh16,   g_gh16);
    cudaGetSymbolAddress((void**)&txn16,  g_txn16);
    cudaGetSymbolAddress((void**)&k16,    g_k16);
    cudaGetSymbolAddress((void**)&v16,    g_v16);
    cudaGetSymbolAddress((void**)&kq16,   g_kq16);
    cudaGetSymbolAddress((void**)&vW16,   g_vW16);
    cudaGetSymbolAddress((void**)&vWT16,  g_vWT16);
    cudaGetSymbolAddress((void**)&attn16, g_attn16);
    cudaGetSymbolAddress((void**)&hid16,  g_hid16);
    cudaGetSymbolAddress((void**)&lnb16,  g_lnb16);
    cudaGetSymbolAddress((void**)&slots16,g_slots16);
    cudaGetSymbolAddress((void**)&Wq16,   g_Wq16);
    cudaGetSymbolAddress((void**)&WqT16,  g_WqT16);
    cudaGetSymbolAddress((void**)&Wk16,   g_Wk16);
    cudaGetSymbolAddress((void**)&Wv16,   g_Wv16);
    cudaGetSymbolAddress((void**)&Wih16,  g_Wih16);
    cudaGetSymbolAddress((void**)&Whh16,  g_Whh16);
    cudaGetSymbolAddress((void**)&W116,   g_W116);
    cudaGetSymbolAddress((void**)&W216,   g_W216);

    // Batched weight + input conversion (one launch)
    f2h_all_kernel<<<F2H_BLOCKS, 256>>>(Wq, Wk, Wv, W_ih, W_hh, W1, W2, inputs,
                                        Wq16, Wk16, Wv16, Wih16, Whh16,
                                        W116, W216, slots16);

    // slots = inputs (fp32 master copy)
    cudaMemcpyAsync(slots, inputs, (size_t)MM * DD * sizeof(float),
                    cudaMemcpyDeviceToDevice);

    // Prologue: texts_n = LN(texts); k/v; folded operands.
    ln_kernel<<<JJ, 256>>>(texts, txn16, gin, bein);
    gemm(txn16, Wk16, 0, k16, JJ, DD, DD, bk, 0, 1.f, 0);
    gemm(txn16, Wv16, 0, v16, JJ, DD, DD, bv, 0, 1.f, 0);
    // kq = k @ Wq  (via WqT as NT B operand)
    transpose_h_kernel<<<dim3(DD / 32, DD / 32), dim3(32, 8)>>>(Wq16, WqT16, DD, DD);
    gemm(k16, WqT16, 0, kq16, JJ, DD, DD, 0, 0, 1.f, 0);
    // dotsb[j] = SCALE * <k[j,:], bq>
    dotsb_kernel<<<JJ, 256>>>(k16, bq, dotsb);
    // vW = v @ W_ih^T  [J, 3D], then vWT [3D, J]
    gemm(v16, Wih16, 0, vW16, JJ, 3 * DD, DD, 0, 0, 1.f, 0);
    transpose_h_kernel<<<dim3(3 * DD / 32, JJ / 32), dim3(32, 8)>>>(vW16, vWT16,
                                                                    JJ, 3 * DD);

    for (int it = 0; it < 3; it++) {
        // lnb = LN(slots)
        ln_kernel<<<MM, 256>>>(slots, lnb16, gsl, besl);

        // dots = SCALE*(lnb @ kq^T) + dotsb  -> fp32  (q GEMM folded away)
        gemm(lnb16, kq16, attn, 0, MM, JJ, DD, dotsb, 0, SCALE, 0);

        // fused softmax over slots axis (+EPS) + renorm over j -> fp16
        softmax_fused_kernel<<<BB, JJ, SMEM_SOFTMAX>>>(attn, attn16);

        // gi = attn @ vW + b_ih  (updates GEMM folded away; K=J=512)
        gemm(attn16, vWT16, 0, gi16, MM, 3 * DD, JJ, b_ih, 0, 1.f, 0);
        // gh = slots @ W_hh^T + b_hh
        gemm(slots16, Whh16, 0, gh16, MM, 3 * DD, DD, b_hh, 0, 1.f, 0);

        // fused GRU update + LayerNorm(ff) -> slots, lnb16
        gru_ln_kernel<<<MM, 256>>>(gi16, gh16, slots, lnb16, gff, beff);

        // FF: slots += relu(LN(slots) @ W1^T + b1) @ W2^T + b2
        gemm(lnb16, W116, 0, hid16, MM, HH, DD, b1, 0, 1.f, 1);
        float* outp = (it == 2) ? (float*)d_out : slots;
        gemm(hid16, W216, outp, slots16, MM, DD, HH, b2, slots, 1.f, 0);
    }
}